// round 2
// baseline (speedup 1.0000x reference)
#include <cuda_runtime.h>
#include <cstdint>

// Hierarchical polarization, restructured:
//   P_0 = pairwise means of Z;  P_{L+1}[G] = mean of (P_L + At_L) over pair
//   out = Z + sum_L At_L[group(s,L)]
// Levels 0..6: level_kernel (f32x2 packed, pair-interleaved smem/global P).
// Levels 7..13: one fused tail_kernel (1 CTA per batch, all levels in smem).
// Final: flat gather over the At pyramid.

typedef unsigned long long u64;

__device__ float4 g_P4[2][2097152];   // ping-pong P buffers (pair-interleaved), 32 MiB each
__device__ float4 g_At4[8388096];     // At pyramid, 14 levels, 128 MiB

__device__ __forceinline__ u64 pack2(float lo, float hi) {
    u64 r; asm("mov.b64 %0, {%1, %2};" : "=l"(r) : "f"(lo), "f"(hi)); return r;
}
__device__ __forceinline__ void unpack2(u64 v, float& lo, float& hi) {
    asm("mov.b64 {%0, %1}, %2;" : "=f"(lo), "=f"(hi) : "l"(v));
}
__device__ __forceinline__ u64 ffma2(u64 a, u64 b, u64 c) {
    u64 d; asm("fma.rn.f32x2 %0, %1, %2, %3;" : "=l"(d) : "l"(a), "l"(b), "l"(c)); return d;
}
__device__ __forceinline__ u64 fadd2(u64 a, u64 b) {
    u64 d; asm("add.rn.f32x2 %0, %1, %2;" : "=l"(d) : "l"(a), "l"(b)); return d;
}

__device__ __forceinline__ float gelu_tanh(float x) {
    // jax.nn.gelu approximate=True; tanh(u) = 1 - 2/(exp(2u)+1)
    float u = 0.7978845608028654f * (x + 0.044715f * x * x * x);
    float e = __expf(2.0f * u);
    float t = 1.0f - __fdividef(2.0f, e + 1.0f);
    return 0.5f * x * (1.0f + t);
}

// ---------------------------------------------------------------------------
// One level (levels 0..6). Block = 32 P-rows = 16 pairs. 256 threads, 8 warps.
// Smem X is pair-interleaved: Xs[pr*256+d] = (x[2pr][d], x[2pr+1][d]) in a u64.
// ---------------------------------------------------------------------------
__global__ void __launch_bounds__(256, 3) level_kernel(
    const float2* __restrict__ Z2,     // used when ping < 0
    int ping,                          // -1: src=Z, out=g_P4[0]; else src=g_P4[ping], out=g_P4[ping^1]
    long long atOff,                   // float offset into At pyramid
    const float* __restrict__ W1, const float* __restrict__ b1,
    const float* __restrict__ W2, const float* __restrict__ b2)
{
    __shared__ u64 Xs[16 * 256];       // 32 KB
    __shared__ u64 Hs[16 * 32];        // 4 KB

    const int t        = threadIdx.x;
    const int rowStart = blockIdx.x * 32;

    // ---- fill smem (pair-interleaved) ----
    if (ping < 0) {
        // level 0: P rows are pair-means of Z rows. Pair pr <-> Z rows 4pr..4pr+3.
        #pragma unroll
        for (int k = 0; k < 8; k++) {
            int task = t + 256 * k;            // 0..2047
            int pr   = task >> 7;              // 0..15
            int dh   = task & 127;             // dim/2
            long long zb = 2LL * rowStart + 4 * pr;
            const float2* zp = Z2 + zb * 128 + dh;
            float2 a0 = zp[0], a1 = zp[128], a2 = zp[256], a3 = zp[384];
            float4 st = make_float4(0.5f * (a0.x + a1.x), 0.5f * (a2.x + a3.x),
                                    0.5f * (a0.y + a1.y), 0.5f * (a2.y + a3.y));
            ((float4*)Xs)[pr * 128 + dh] = st; // conflict-free, consecutive per warp
        }
    } else {
        // pair-interleaved copy: block's 16 pairs are contiguous 32KB in P2in
        const float4* s = (const float4*)g_P4[ping] + (long long)rowStart * 64;
        #pragma unroll
        for (int k = 0; k < 8; k++)
            ((float4*)Xs)[t + 256 * k] = s[t + 256 * k];
    }
    __syncthreads();

    const int lane = t & 31;
    const int wp   = t >> 5;
    const int pr0  = 2 * wp;           // warp owns pairs pr0, pr0+1 (rows 4wp..4wp+3)

    // ---- phase 1: H = gelu(X @ W1 + b1), f32x2 over row pairs ----
    {
        u64 acc0 = 0ULL, acc1 = 0ULL;
        const float* w1p = W1 + lane;
        const u64* x0 = Xs + pr0 * 256;
        #pragma unroll 8
        for (int d = 0; d < 256; d++) {
            float w = w1p[d * 32];             // coalesced, L1-resident
            u64 w2r = pack2(w, w);
            acc0 = ffma2(x0[d],       w2r, acc0);
            acc1 = ffma2(x0[256 + d], w2r, acc1);
        }
        float bb = b1[lane];
        float s0, s1, s2, s3;
        unpack2(acc0, s0, s1); unpack2(acc1, s2, s3);
        Hs[pr0 * 32 + lane]       = pack2(gelu_tanh(s0 + bb), gelu_tanh(s1 + bb));
        Hs[(pr0 + 1) * 32 + lane] = pack2(gelu_tanh(s2 + bb), gelu_tanh(s3 + bb));
    }
    __syncwarp();   // Hs pairs pr0,pr0+1 produced & consumed by this warp only

    // ---- phase 3: At = H @ W2 + b2; write At; X += At ----
    {
        float* At = ((float*)g_At4) + atOff + (long long)rowStart * 256;
        u64* XsP0 = Xs + pr0 * 256;
        u64* XsP1 = XsP0 + 256;
        const u64* H0 = Hs + pr0 * 32;
        const u64* H1 = H0 + 32;
        #pragma unroll
        for (int k = 0; k < 8; k++) {
            int d = lane + 32 * k;
            float bv = b2[d];
            u64 acc0 = pack2(bv, bv), acc1 = acc0;
            const float* w2p = W2 + d;
            #pragma unroll 8
            for (int j = 0; j < 32; j++) {
                float w = w2p[j * 256];        // coalesced, L1-resident
                u64 wr = pack2(w, w);
                acc0 = ffma2(H0[j], wr, acc0);
                acc1 = ffma2(H1[j], wr, acc1);
            }
            float a0, a1, a2, a3;
            unpack2(acc0, a0, a1); unpack2(acc1, a2, a3);
            int r4 = 4 * wp;
            At[(r4 + 0) * 256 + d] = a0;
            At[(r4 + 1) * 256 + d] = a1;
            At[(r4 + 2) * 256 + d] = a2;
            At[(r4 + 3) * 256 + d] = a3;
            XsP0[d] = fadd2(XsP0[d], acc0);
            XsP1[d] = fadd2(XsP1[d], acc1);
        }
    }
    __syncthreads();

    // ---- phase 4: next-level P = pair means, written pair-interleaved ----
    {
        float2* Pout = (float2*)g_P4[(ping < 0) ? 0 : (ping ^ 1)];
        long long qBase = rowStart >> 2;     // 8 output pairs per block
        #pragma unroll
        for (int k = 0; k < 8; k++) {
            int idx = t + 256 * k;           // 0..2047
            int ql  = idx >> 8;              // 0..7
            int d   = idx & 255;
            float lo, hi;
            unpack2(Xs[(2 * ql) * 256 + d], lo, hi);
            float mA = 0.5f * (lo + hi);
            unpack2(Xs[(2 * ql + 1) * 256 + d], lo, hi);
            float mB = 0.5f * (lo + hi);
            Pout[(qBase + ql) * 256 + d] = make_float2(mA, mB);
        }
    }
}

// ---------------------------------------------------------------------------
// Fused tail: levels 7..13. One block per batch (8 blocks). All data in smem.
// Region A = rows 0..63, region B = rows 64..95 (ping-pong across levels).
// ---------------------------------------------------------------------------
#define TAIL_SMEM (96 * 256 * 4 + 64 * 32 * 4)

__global__ void __launch_bounds__(256) tail_kernel(
    long long atOff7,
    const float* __restrict__ W1a, const float* __restrict__ b1a,
    const float* __restrict__ W2a, const float* __restrict__ b2a)
{
    extern __shared__ float sh[];
    float* H = sh + 96 * 256;

    const int b    = blockIdx.x;
    const int t    = threadIdx.x;
    const int lane = t & 31;
    const int wp   = t >> 5;
    float* AtBase = (float*)g_At4;

    // load level-7 input: pair-interleaved P from level 6 (buffer 0)
    {
        const float2* P2in = (const float2*)g_P4[0];
        #pragma unroll
        for (int k = 0; k < 32; k++) {
            int e  = t + 256 * k;            // 0..8191 float2 elements
            int pr = e >> 8;
            int d  = e & 255;
            float2 v = P2in[b * 8192 + e];
            sh[(2 * pr) * 256 + d]     = v.x;
            sh[(2 * pr + 1) * 256 + d] = v.y;
        }
    }
    __syncthreads();

    long long atOff = atOff7;
    int xbase = 0;
    int ng = 64;                             // rows per batch at level 7
    for (int L = 7; L < 14; L++) {
        int tt = (L < 10) ? L : 9;
        const float* w1 = W1a + (long long)tt * 8192;
        const float* v1 = b1a + tt * 32;
        const float* w2 = W2a + (long long)tt * 8192;
        const float* v2 = b2a + tt * 256;
        float* Xc = sh + xbase * 256;

        for (int r = wp; r < ng; r += 8) {
            // h = gelu(x @ W1 + b1), 4 partial accumulators to break the chain
            float a0 = 0.f, a1 = 0.f, a2 = 0.f, a3 = 0.f;
            const float* xr = Xc + r * 256;
            #pragma unroll 4
            for (int d = 0; d < 256; d += 4) {
                a0 = fmaf(xr[d + 0], w1[(d + 0) * 32 + lane], a0);
                a1 = fmaf(xr[d + 1], w1[(d + 1) * 32 + lane], a1);
                a2 = fmaf(xr[d + 2], w1[(d + 2) * 32 + lane], a2);
                a3 = fmaf(xr[d + 3], w1[(d + 3) * 32 + lane], a3);
            }
            H[r * 32 + lane] = gelu_tanh((a0 + a1) + (a2 + a3) + v1[lane]);
        }
        __syncwarp();
        for (int r = wp; r < ng; r += 8) {
            long long grow = atOff + ((long long)b * ng + r) * 256;
            float* xr = Xc + r * 256;
            const float* hr = H + r * 32;
            #pragma unroll
            for (int k = 0; k < 8; k++) {
                int d = lane + 32 * k;
                float a0 = v2[d], a1 = 0.f;
                #pragma unroll 4
                for (int j = 0; j < 32; j += 2) {
                    a0 = fmaf(hr[j],     w2[j * 256 + d],       a0);
                    a1 = fmaf(hr[j + 1], w2[(j + 1) * 256 + d], a1);
                }
                float a = a0 + a1;
                AtBase[grow + d] = a;
                xr[d] += a;
            }
        }
        atOff += 8LL * ng * 256;
        __syncthreads();
        if (L < 13) {
            int ng2 = ng >> 1;
            float* Xn = sh + ((xbase == 0) ? 64 : 0) * 256;
            for (int e = t; e < ng2 * 256; e += 256) {
                int g = e >> 8, d = e & 255;
                Xn[g * 256 + d] = 0.5f * (Xc[(2 * g) * 256 + d] + Xc[(2 * g + 1) * 256 + d]);
            }
            xbase = (xbase == 0) ? 64 : 0;
            ng = ng2;
            __syncthreads();
        }
    }
}

// ---------------------------------------------------------------------------
// out = Z + sum over 14 levels of At[level][b, s>>(L+1), d]
// ---------------------------------------------------------------------------
__global__ void __launch_bounds__(256) final_kernel(
    const float4* __restrict__ Z4, float4* __restrict__ out4)
{
    int i   = blockIdx.x * 256 + threadIdx.x;  // < 8388608 float4 elements
    int d4  = i & 63;
    int row = i >> 6;          // b*16384 + s
    int b   = row >> 14;
    int s   = row & 16383;

    float4 acc = Z4[i];
    long long off4 = 0;
    int ng = 8192;
    #pragma unroll
    for (int L = 0; L < 14; L++) {
        int g = s >> (L + 1);
        float4 a = g_At4[off4 + (long long)(b * ng + g) * 64 + d4];
        acc.x += a.x; acc.y += a.y; acc.z += a.z; acc.w += a.w;
        off4 += 512LL * ng;
        ng >>= 1;
    }
    out4[i] = acc;
}

extern "C" void kernel_launch(void* const* d_in, const int* in_sizes, int n_in,
                              void* d_out, int out_size)
{
    const float* Z  = (const float*)d_in[0];
    const float* W1 = (const float*)d_in[1];
    const float* b1 = (const float*)d_in[2];
    const float* W2 = (const float*)d_in[3];
    const float* b2 = (const float*)d_in[4];

    cudaFuncSetAttribute(tail_kernel, cudaFuncAttributeMaxDynamicSharedMemorySize, TAIL_SMEM);

    long long atOff = 0;
    for (int L = 0; L < 7; L++) {
        int rows   = 65536 >> L;
        int ping   = (L == 0) ? -1 : ((L - 1) & 1);
        int blocks = rows / 32;
        level_kernel<<<blocks, 256>>>((const float2*)Z, ping, atOff,
                                      W1 + (long long)L * 8192,
                                      b1 + L * 32,
                                      W2 + (long long)L * 8192,
                                      b2 + L * 256);
        atOff += (long long)rows * 256;
    }
    tail_kernel<<<8, 256, TAIL_SMEM>>>(atOff, W1, b1, W2, b2);
    final_kernel<<<32768, 256>>>((const float4*)Z, (float4*)d_out);
}